// round 17
// baseline (speedup 1.0000x reference)
#include <cuda_runtime.h>
#include <cuda_fp16.h>
#include <math.h>
#include <stdint.h>

// Problem constants (fixed shapes)
#define BSZ 2
#define HWN 4096
#define CD  512
#define NBROWS (BSZ*HWN)      // 8192
#define NGROUPS 32

// ---------------------------------------------------------------------------
// Scratch (device globals; no allocations)
// ---------------------------------------------------------------------------
__device__ __half g_xn16 [(size_t)NBROWS*CD];
__device__ __half g_qkv16[(size_t)3*NBROWS*CD];        // q16 | k16 | v16
__device__ __half g_wt16 [(size_t)4*CD*CD];            // wqT|wkT|wvT|wpT (half)
__device__ __half g_vt16 [(size_t)BSZ*CD*HWN];         // v transposed per batch
__device__ __half g_attn16[(size_t)BSZ*HWN*HWN];       // fp16 scores -> weights (67 MB)
__device__ __half g_ao16 [(size_t)NBROWS*CD];
__device__ float  g_b3   [3*CD];                       // bq|bk|bv packed
__device__ float  g_mean [BSZ*NGROUPS];
__device__ float  g_rstd [BSZ*NGROUPS];

// ---------------------------------------------------------------------------
// helpers
// ---------------------------------------------------------------------------
__device__ __forceinline__ uint32_t smem_u32(const void* p) {
    uint32_t a;
    asm("{ .reg .u64 t; cvta.to.shared.u64 t, %1; cvt.u32.u64 %0, t; }" : "=r"(a) : "l"(p));
    return a;
}
__device__ __forceinline__ void cp16(uint32_t dst, const void* src) {
    asm volatile("cp.async.cg.shared.global [%0], [%1], 16;" :: "r"(dst), "l"(src));
}
#define CP_COMMIT() asm volatile("cp.async.commit_group;")
#define CP_WAIT1()  asm volatile("cp.async.wait_group 1;")

__device__ __forceinline__ void ldmx4(uint32_t r[4], uint32_t addr) {
    asm volatile("ldmatrix.sync.aligned.m8n8.x4.shared.b16 {%0,%1,%2,%3}, [%4];"
        : "=r"(r[0]), "=r"(r[1]), "=r"(r[2]), "=r"(r[3]) : "r"(addr));
}
__device__ __forceinline__ void mma_f16(float c[4], const uint32_t a[4], const uint32_t b[2]) {
    asm volatile(
        "mma.sync.aligned.m16n8k16.row.col.f32.f16.f16.f32 "
        "{%0,%1,%2,%3}, {%4,%5,%6,%7}, {%8,%9}, {%0,%1,%2,%3};"
        : "+f"(c[0]), "+f"(c[1]), "+f"(c[2]), "+f"(c[3])
        : "r"(a[0]), "r"(a[1]), "r"(a[2]), "r"(a[3]), "r"(b[0]), "r"(b[1]));
}

// ---------------------------------------------------------------------------
// GroupNorm stats (+ fused bias pack in block 64)
// ---------------------------------------------------------------------------
__global__ void gn_stats_bias(const float* __restrict__ x,
                              float* __restrict__ mean, float* __restrict__ rstd,
                              const float* __restrict__ bq, const float* __restrict__ bk,
                              const float* __restrict__ bv, float* __restrict__ b3) {
    if (blockIdx.x == 64) {
        for (int i = threadIdx.x; i < CD; i += 256) {
            b3[i] = bq[i]; b3[CD + i] = bk[i]; b3[2*CD + i] = bv[i];
        }
        return;
    }
    __shared__ float shs[8], shss[8];
    const int bg = blockIdx.x;
    const int b = bg >> 5, g = bg & 31;
    const float4* xb = (const float4*)x + (size_t)b*524288 + g*4;
    float s = 0.f, ss = 0.f;
    for (int i = threadIdx.x; i < 16384; i += 256) {
        int n = i >> 2, j = i & 3;
        float4 vv = xb[(size_t)n*128 + j];
        s  += vv.x + vv.y + vv.z + vv.w;
        ss += vv.x*vv.x + vv.y*vv.y + vv.z*vv.z + vv.w*vv.w;
    }
    #pragma unroll
    for (int o = 16; o; o >>= 1) {
        s  += __shfl_xor_sync(0xffffffffu, s,  o);
        ss += __shfl_xor_sync(0xffffffffu, ss, o);
    }
    if ((threadIdx.x & 31) == 0) { shs[threadIdx.x>>5] = s; shss[threadIdx.x>>5] = ss; }
    __syncthreads();
    if (threadIdx.x == 0) {
        s = 0.f; ss = 0.f;
        #pragma unroll
        for (int w = 0; w < 8; w++) { s += shs[w]; ss += shss[w]; }
        float m   = s * (1.f/65536.f);
        float var = ss * (1.f/65536.f) - m*m;
        mean[bg] = m;
        rstd[bg] = rsqrtf(var + 1e-5f);
    }
}

// GroupNorm normalize -> fp16 output
__global__ void gn_norm(const float* __restrict__ x,
                        const float* __restrict__ gamma, const float* __restrict__ beta,
                        const float* __restrict__ mean, const float* __restrict__ rstd,
                        __half* __restrict__ xn) {
    const int idx = blockIdx.x * blockDim.x + threadIdx.x;   // float4 index
    float4 v = ((const float4*)x)[idx];
    const int c4 = idx & 127;
    const int b  = idx >> 19;
    const int g  = c4 >> 2;
    const int bg = b * 32 + g;
    const float m = mean[bg], r = rstd[bg];
    const float4 ga = ((const float4*)gamma)[c4];
    const float4 be = ((const float4*)beta)[c4];
    __half2 h0 = __float22half2_rn(make_float2((v.x - m)*r*ga.x + be.x, (v.y - m)*r*ga.y + be.y));
    __half2 h1 = __float22half2_rn(make_float2((v.z - m)*r*ga.z + be.z, (v.w - m)*r*ga.w + be.w));
    uint2 o = make_uint2(*(uint32_t*)&h0, *(uint32_t*)&h1);
    ((uint2*)xn)[idx] = o;
}

// 4 weight transposes fused (z selects weight), fp32 in -> fp16 out
__global__ void wtrans4(const float* __restrict__ w0, const float* __restrict__ w1,
                        const float* __restrict__ w2, const float* __restrict__ w3,
                        __half* __restrict__ out) {
    __shared__ float t[32][33];
    const float* src = blockIdx.z == 0 ? w0 : blockIdx.z == 1 ? w1 : blockIdx.z == 2 ? w2 : w3;
    __half* dst = out + (size_t)blockIdx.z * CD * CD;
    int c0 = blockIdx.x * 32, r0 = blockIdx.y * 32;
    int xx = threadIdx.x;
    #pragma unroll
    for (int y = threadIdx.y; y < 32; y += 8)
        t[y][xx] = src[(size_t)(r0 + y) * CD + c0 + xx];
    __syncthreads();
    #pragma unroll
    for (int y = threadIdx.y; y < 32; y += 8)
        dst[(size_t)(c0 + y) * CD + r0 + xx] = __float2half_rn(t[xx][y]);
}

// v16 [b][n][c] -> vt16 [b][c][n]
__global__ void vtrans_h(const __half* __restrict__ in, __half* __restrict__ out) {
    __shared__ __half t[32][33];
    const __half* inz = in + (size_t)blockIdx.z * HWN * CD;
    __half* outz = out + (size_t)blockIdx.z * CD * HWN;
    int c0 = blockIdx.x * 32, r0 = blockIdx.y * 32;
    int xx = threadIdx.x;
    #pragma unroll
    for (int y = threadIdx.y; y < 32; y += 8)
        t[y][xx] = inz[(size_t)(r0 + y) * CD + c0 + xx];
    __syncthreads();
    #pragma unroll
    for (int y = threadIdx.y; y < 32; y += 8)
        outz[(size_t)(c0 + y) * HWN + r0 + xx] = t[xx][y];
}

// ---------------------------------------------------------------------------
// fp16 NT GEMM, BK=64, cp.async 3-stage ring (16KB stages, 96KB total):
//   C[m][n] = alpha * sum_k A[m][k]*Bt[n][k]  (+bias[n]) (+res[m][n])
// CTA 128x128, BK=64 (4 k16 steps), 256 thr = 8 warps (2m x 4n), warp 64x32.
// SMEM rows 128B (64 half), 16B chunk c stored at (c ^ (row&7)) -> each
// 8-lane ldmatrix phase covers all 32 banks.  One barrier per 128 MMAs/warp.
// 16-row offset within a stage = 16*128B = 2048B (A: mi*2048, B: p*2048).
// ---------------------------------------------------------------------------
#define STAGE_BYTES 16384
#define GEMM_SMEM (3 * STAGE_BYTES * 2)     // 96 KB

template<bool BIAS, bool RES, bool HOUT>
__global__ __launch_bounds__(256, 2)
void gemm_h(const __half* __restrict__ A, const __half* __restrict__ Bt,
            const float* __restrict__ bias, const float* __restrict__ res,
            void* __restrict__ Cptr,
            int K, int lda, int ldb, int ldc, float alpha,
            size_t zA, size_t zB, size_t zC, size_t zBias) {
    extern __shared__ uint32_t dynsm[];

    A  += blockIdx.z * zA;
    Bt += blockIdx.z * zB;
    const float* biasz = BIAS ? (bias + blockIdx.z * zBias) : bias;
    float*  Cf = (float*)Cptr  + (HOUT ? 0 : blockIdx.z * zC);
    __half* Ch = (__half*)Cptr + (HOUT ? blockIdx.z * zC : 0);

    const int tid = threadIdx.x;
    const int wid = tid >> 5;
    const int lane = tid & 31;
    const int gid = lane >> 2;
    const int tg  = lane & 3;
    const int wm = (wid & 1) * 64;
    const int wn = (wid >> 1) * 32;
    const int rowBlock = blockIdx.y * 128;
    const int colBlock = blockIdx.x * 128;

    // ---- cp.async staging: 4 chunks (16B each) per thread per operand
    const int srow = tid >> 1;            // 0..127
    const int scb  = (tid & 1) * 4;       // chunk base 0 or 4
    uint32_t sd[4];
    #pragma unroll
    for (int i = 0; i < 4; i++)
        sd[i] = (uint32_t)srow * 128 + (uint32_t)(((scb + i) ^ (srow & 7)) * 16);
    const __half* Asrc = A  + (size_t)(rowBlock + srow) * lda + scb * 8;
    const __half* Bsrc = Bt + (size_t)(colBlock + srow) * ldb + scb * 8;
    const uint32_t aS = smem_u32(dynsm);
    const uint32_t bS = aS + 3 * STAGE_BYTES;

    // ---- ldmatrix per-lane fragment base values
    const int rowA = wm + ((lane >> 3) & 1) * 8 + (lane & 7);
    const uint32_t cA0 = (lane >> 4) & 1;
    const uint32_t rmA = rowA & 7;
    const uint32_t baseA = (uint32_t)rowA * 128;
    const int rowB = wn + ((lane >> 4) & 1) * 8 + (lane & 7);
    const uint32_t cB0 = (lane >> 3) & 1;
    const uint32_t rmB = rowB & 7;
    const uint32_t baseB = (uint32_t)rowB * 128;

    float acc[4][4][4];
    #pragma unroll
    for (int mi = 0; mi < 4; mi++)
        #pragma unroll
        for (int ni = 0; ni < 4; ni++)
            #pragma unroll
            for (int r = 0; r < 4; r++) acc[mi][ni][r] = 0.f;

    const int T = K >> 6;     // BK=64 tiles (K=512 -> 8, K=4096 -> 64)

    // prologue: stage tiles 0 and 1
    #pragma unroll
    for (int st = 0; st < 2; st++) {
        #pragma unroll
        for (int i = 0; i < 4; i++) {
            cp16(aS + st * STAGE_BYTES + sd[i], Asrc + st * 64 + i * 8);
            cp16(bS + st * STAGE_BYTES + sd[i], Bsrc + st * 64 + i * 8);
        }
        CP_COMMIT();
    }
    CP_WAIT1();            // tile 0 resident
    __syncthreads();

    int s = 0;
    for (int t = 0; t < T; t++) {
        // issue tile t+2 into stage (s+2)%3 (overlaps with compute below)
        if (t + 2 < T) {
            int s2 = s + 2; if (s2 >= 3) s2 -= 3;
            const int kh = (t + 2) * 64;
            #pragma unroll
            for (int i = 0; i < 4; i++) {
                cp16(aS + s2 * STAGE_BYTES + sd[i], Asrc + kh + i * 8);
                cp16(bS + s2 * STAGE_BYTES + sd[i], Bsrc + kh + i * 8);
            }
        }
        CP_COMMIT();       // one group per iteration, always

        const uint32_t aBase = aS + s * STAGE_BYTES;
        const uint32_t bBase = bS + s * STAGE_BYTES;

        #pragma unroll
        for (int ks = 0; ks < 4; ks++) {
            const uint32_t ks2 = (uint32_t)(ks * 2);
            uint32_t af[4][4], bf[2][4];
            #pragma unroll
            for (int mi = 0; mi < 4; mi++)
                ldmx4(af[mi], aBase + baseA + mi * 2048 + (((ks2 | cA0) ^ rmA) << 4));
            #pragma unroll
            for (int p = 0; p < 2; p++)
                ldmx4(bf[p], bBase + baseB + p * 2048 + (((ks2 | cB0) ^ rmB) << 4));
            #pragma unroll
            for (int mi = 0; mi < 4; mi++)
                #pragma unroll
                for (int ni = 0; ni < 4; ni++)
                    mma_f16(acc[mi][ni], af[mi], &bf[ni >> 1][(ni & 1) * 2]);
        }

        CP_WAIT1();        // tile t+1 resident; stage s now safely reusable
        __syncthreads();
        s++; if (s == 3) s = 0;
    }

    // epilogue (fragment layout identical to validated scalar version)
    #pragma unroll
    for (int mi = 0; mi < 4; mi++) {
        #pragma unroll
        for (int half = 0; half < 2; half++) {
            const size_t r = (size_t)(rowBlock + wm + mi * 16 + gid + half * 8);
            #pragma unroll
            for (int ni = 0; ni < 4; ni++) {
                const size_t c = (size_t)(colBlock + wn + ni * 8 + 2 * tg);
                float ox = acc[mi][ni][half * 2 + 0] * alpha;
                float oy = acc[mi][ni][half * 2 + 1] * alpha;
                if (BIAS) {
                    const float2 bb = *(const float2*)(biasz + c);
                    ox += bb.x; oy += bb.y;
                }
                if (RES) {
                    const float2 rr = *(const float2*)(res + r * ldc + c);
                    ox += rr.x; oy += rr.y;
                }
                if (HOUT) {
                    __half2 h = __float22half2_rn(make_float2(ox, oy));
                    *(__half2*)(Ch + r * ldc + c) = h;
                } else {
                    *(float2*)(Cf + r * ldc + c) = make_float2(ox, oy);
                }
            }
        }
    }
}

// ---------------------------------------------------------------------------
// Row softmax, in-place on fp16 scores (fp32 math internally)
// ---------------------------------------------------------------------------
__global__ void softmax_h(__half* __restrict__ S) {
    __shared__ float sh[8];
    const size_t row = blockIdx.x;
    __half* p = S + row * 4096;
    const int tid = threadIdx.x;
    float v[16];
    float mx = -1e30f;
    #pragma unroll
    for (int i = 0; i < 4; i++) {
        uint2 raw = ((const uint2*)p)[tid + i*256];
        float2 a = __half22float2(*(__half2*)&raw.x);
        float2 b = __half22float2(*(__half2*)&raw.y);
        v[i*4+0] = a.x; v[i*4+1] = a.y; v[i*4+2] = b.x; v[i*4+3] = b.y;
        mx = fmaxf(mx, fmaxf(fmaxf(a.x, a.y), fmaxf(b.x, b.y)));
    }
    #pragma unroll
    for (int o = 16; o; o >>= 1) mx = fmaxf(mx, __shfl_xor_sync(0xffffffffu, mx, o));
    if ((tid & 31) == 0) sh[tid >> 5] = mx;
    __syncthreads();
    mx = sh[0];
    #pragma unroll
    for (int w = 1; w < 8; w++) mx = fmaxf(mx, sh[w]);

    float sum = 0.f;
    #pragma unroll
    for (int i = 0; i < 16; i++) { v[i] = expf(v[i] - mx); sum += v[i]; }
    #pragma unroll
    for (int o = 16; o; o >>= 1) sum += __shfl_xor_sync(0xffffffffu, sum, o);
    __syncthreads();
    if ((tid & 31) == 0) sh[tid >> 5] = sum;
    __syncthreads();
    sum = 0.f;
    #pragma unroll
    for (int w = 0; w < 8; w++) sum += sh[w];
    const float inv = 1.f / sum;
    #pragma unroll
    for (int i = 0; i < 4; i++) {
        __half2 h0 = __float22half2_rn(make_float2(v[i*4+0] * inv, v[i*4+1] * inv));
        __half2 h1 = __float22half2_rn(make_float2(v[i*4+2] * inv, v[i*4+3] * inv));
        ((uint2*)p)[tid + i*256] = make_uint2(*(uint32_t*)&h0, *(uint32_t*)&h1);
    }
}

// ---------------------------------------------------------------------------
// launch
// ---------------------------------------------------------------------------
extern "C" void kernel_launch(void* const* d_in, const int* in_sizes, int n_in,
                              void* d_out, int out_size) {
    const float* x     = (const float*)d_in[0];
    const float* gamma = (const float*)d_in[1];
    const float* beta  = (const float*)d_in[2];
    const float* wq    = (const float*)d_in[3];
    const float* bq    = (const float*)d_in[4];
    const float* wk    = (const float*)d_in[5];
    const float* bk    = (const float*)d_in[6];
    const float* wv    = (const float*)d_in[7];
    const float* bv    = (const float*)d_in[8];
    const float* wp    = (const float*)d_in[9];
    const float* bp    = (const float*)d_in[10];
    float* out = (float*)d_out;

    __half *xn16, *qkv16, *wt16, *vt16, *attn16, *ao16;
    float *b3, *mean, *rstd;
    cudaGetSymbolAddress((void**)&xn16,   g_xn16);
    cudaGetSymbolAddress((void**)&qkv16,  g_qkv16);
    cudaGetSymbolAddress((void**)&wt16,   g_wt16);
    cudaGetSymbolAddress((void**)&vt16,   g_vt16);
    cudaGetSymbolAddress((void**)&attn16, g_attn16);
    cudaGetSymbolAddress((void**)&ao16,   g_ao16);
    cudaGetSymbolAddress((void**)&b3,     g_b3);
    cudaGetSymbolAddress((void**)&mean,   g_mean);
    cudaGetSymbolAddress((void**)&rstd,   g_rstd);
    __half* q16 = qkv16;
    __half* k16 = qkv16 + (size_t)NBROWS*CD;
    __half* v16 = qkv16 + (size_t)2*NBROWS*CD;
    __half* wpT16 = wt16 + (size_t)3*CD*CD;

    // allow 96 KB dynamic SMEM for the GEMM instantiations (host-side, capture-safe)
    cudaFuncSetAttribute(gemm_h<true,  false, true >, cudaFuncAttributeMaxDynamicSharedMemorySize, GEMM_SMEM);
    cudaFuncSetAttribute(gemm_h<false, false, true >, cudaFuncAttributeMaxDynamicSharedMemorySize, GEMM_SMEM);
    cudaFuncSetAttribute(gemm_h<true,  true,  false>, cudaFuncAttributeMaxDynamicSharedMemorySize, GEMM_SMEM);

    // 1) GroupNorm stats + bias pack
    gn_stats_bias<<<65, 256>>>(x, mean, rstd, bq, bk, bv, b3);

    // 2) normalize -> fp16
    gn_norm<<<(NBROWS*CD/4)/256, 256>>>(x, gamma, beta, mean, rstd, xn16);

    // 3) weight transposes (fused, z=4) -> fp16
    wtrans4<<<dim3(CD/32, CD/32, 4), dim3(32, 8)>>>(wq, wk, wv, wp, wt16);

    // 4) fused qkv projections: z selects (wT, bias, out slab)
    gemm_h<true, false, true><<<dim3(CD/128, NBROWS/128, 3), 256, GEMM_SMEM>>>(
        xn16, wt16, b3, nullptr, qkv16, CD, CD, CD, CD, 1.f,
        0, (size_t)CD*CD, (size_t)NBROWS*CD, (size_t)CD);

    // 5) scores = q k^T * 1/sqrt(C) -> fp16 (direct)
    const float scale = 0.044194173824159216f;
    gemm_h<false, false, true><<<dim3(HWN/128, HWN/128, BSZ), 256, GEMM_SMEM>>>(
        q16, k16, nullptr, nullptr, attn16, CD, CD, CD, HWN, scale,
        (size_t)HWN*CD, (size_t)HWN*CD, (size_t)HWN*HWN, 0);

    // 6) v transpose per batch (half)
    vtrans_h<<<dim3(CD/32, HWN/32, BSZ), dim3(32, 8)>>>(v16, vt16);

    // 7) softmax in-place on fp16 scores
    softmax_h<<<NBROWS, 256>>>(attn16);

    // 8) ao = attn @ v (K=4096, all-half inputs) -> fp16
    gemm_h<false, false, true><<<dim3(CD/128, HWN/128, BSZ), 256, GEMM_SMEM>>>(
        attn16, vt16, nullptr, nullptr, ao16, HWN, HWN, HWN, CD, 1.f,
        (size_t)HWN*HWN, (size_t)CD*HWN, (size_t)HWN*CD, 0);

    // 9) final projection + bias + residual -> fp32 d_out
    gemm_h<true, true, false><<<dim3(CD/128, NBROWS/128, 1), 256, GEMM_SMEM>>>(
        ao16, wpT16, bp, x, out, CD, CD, CD, CD, 1.f, 0, 0, 0, 0);
}